// round 8
// baseline (speedup 1.0000x reference)
#include <cuda_runtime.h>
#include <cuda_bf16.h>
#include <cstdint>

#define B_   256
#define T_   10
#define BT_  2560
#define HW_  49
#define VD_  512
#define AD_  128
#define HD_  256

// ---------------------------------------------------------------------------
// Scratch (__device__ globals — allocation-free)
// ---------------------------------------------------------------------------
__device__ float g_aq1[BT_ * VD_];
__device__ float g_aq2[BT_ * HD_];
__device__ float g_m1 [BT_ * VD_];
__device__ float g_scale[BT_ * VD_];
__device__ float g_part[BT_ * 2 * 64];   // per-clip, per-n-half row partials

// Pre-split bf16 weight images: [n_chunk][k_chunk(8)][128 n-rows][72 k]
__device__ __align__(16) __nv_bfloat16 g_W1h[4 * 8 * 128 * 72];
__device__ __align__(16) __nv_bfloat16 g_W1l[4 * 8 * 128 * 72];
__device__ __align__(16) __nv_bfloat16 g_W2h[2 * 8 * 128 * 72];
__device__ __align__(16) __nv_bfloat16 g_W2l[2 * 8 * 128 * 72];

#define CHUNK_ELEMS (128 * 72)
#define ROWB 144                         // 72 bf16 per row
#define MT_STRIDE (16 * ROWB)
// double-buffered SMEM: per buffer A_h@0  A_l@18432  W_h@36864  W_l@55296
#define BUF_BYTES 73728
#define SMEM_TOT  (2 * BUF_BYTES)        // 147456

// ---------------------------------------------------------------------------
// Helpers (plain sm_103-safe PTX only)
// ---------------------------------------------------------------------------
__device__ __forceinline__ uint32_t smem_u32(const void* p) {
    uint32_t a;
    asm("{ .reg .u64 t; cvta.to.shared.u64 t, %1; cvt.u32.u64 %0, t; }"
        : "=r"(a) : "l"(p));
    return a;
}
__device__ __forceinline__ void ldmx4(uint32_t addr, uint32_t r[4]) {
    asm volatile("ldmatrix.sync.aligned.m8n8.x4.shared.b16 {%0,%1,%2,%3}, [%4];"
                 : "=r"(r[0]), "=r"(r[1]), "=r"(r[2]), "=r"(r[3]) : "r"(addr));
}
__device__ __forceinline__ void mma_bf16(float d[4], const uint32_t a[4],
                                         uint32_t b0, uint32_t b1) {
    asm volatile(
        "mma.sync.aligned.m16n8k16.row.col.f32.bf16.bf16.f32 "
        "{%0,%1,%2,%3},{%4,%5,%6,%7},{%8,%9},{%0,%1,%2,%3};"
        : "+f"(d[0]), "+f"(d[1]), "+f"(d[2]), "+f"(d[3])
        : "r"(a[0]), "r"(a[1]), "r"(a[2]), "r"(a[3]), "r"(b0), "r"(b1));
}
__device__ __forceinline__ void cp16(uint32_t dst, const void* src) {
    asm volatile("cp.async.cg.shared.global [%0], [%1], 16;" :: "r"(dst), "l"(src));
}
#define CP_COMMIT() asm volatile("cp.async.commit_group;" ::: "memory")
#define CP_WAIT0()  asm volatile("cp.async.wait_group 0;" ::: "memory")

__device__ __forceinline__ void split_store(char* Ah, char* Al, int r, int q,
                                            float x0, float x1, float x2, float x3) {
    __nv_bfloat16 h0 = __float2bfloat16(x0), h1 = __float2bfloat16(x1);
    __nv_bfloat16 h2 = __float2bfloat16(x2), h3 = __float2bfloat16(x3);
    __nv_bfloat16 l0 = __float2bfloat16(x0 - __bfloat162float(h0));
    __nv_bfloat16 l1 = __float2bfloat16(x1 - __bfloat162float(h1));
    __nv_bfloat16 l2 = __float2bfloat16(x2 - __bfloat162float(h2));
    __nv_bfloat16 l3 = __float2bfloat16(x3 - __bfloat162float(h3));
    __nv_bfloat162 p;
    char* dh = Ah + r * ROWB + q * 8;
    char* dl = Al + r * ROWB + q * 8;
    p.x = h0; p.y = h1; *(__nv_bfloat162*)dh = p;
    p.x = h2; p.y = h3; *(__nv_bfloat162*)(dh + 4) = p;
    p.x = l0; p.y = l1; *(__nv_bfloat162*)dl = p;
    p.x = l2; p.y = l3; *(__nv_bfloat162*)(dl + 4) = p;
}

// ---------------------------------------------------------------------------
// k0: split Wv1/Wv2 into bf16 hi/lo padded tile images (unchanged)
// ---------------------------------------------------------------------------
__global__ void __launch_bounds__(256)
k0_wconv(const float* __restrict__ Wv1, const float* __restrict__ Wv2)
{
    int idx = blockIdx.x * 256 + threadIdx.x;
    if (idx < 512 * 512) {
        int c = idx >> 9, k = idx & 511;
        float v = Wv1[idx];
        __nv_bfloat16 h = __float2bfloat16(v);
        __nv_bfloat16 l = __float2bfloat16(v - __bfloat162float(h));
        int nc = c >> 7, nl = c & 127, kc = k >> 6, kk = k & 63;
        size_t d = ((size_t)(nc * 8 + kc) * 128 + nl) * 72 + kk;
        g_W1h[d] = h; g_W1l[d] = l;
    } else if (idx < 512 * 512 + 256 * 512) {
        int e = idx - 512 * 512;
        int j = e >> 9, k = e & 511;
        float v = Wv2[e];
        __nv_bfloat16 h = __float2bfloat16(v);
        __nv_bfloat16 l = __float2bfloat16(v - __bfloat162float(h));
        int nc = j >> 7, nl = j & 127, kc = k >> 6, kk = k & 63;
        size_t d = ((size_t)(nc * 8 + kc) * 128 + nl) * 72 + kk;
        g_W2h[d] = h; g_W2l[d] = l;
    }
}

// ---------------------------------------------------------------------------
// k1: audio features (unchanged — proven)
// ---------------------------------------------------------------------------
__global__ void __launch_bounds__(256)
k1_audio(const float* __restrict__ audio,
         const float* __restrict__ Wa1, const float* __restrict__ ba1,
         const float* __restrict__ Wa2, const float* __restrict__ ba2)
{
    __shared__ __align__(16) float af[32][AD_];
    const int tid = threadIdx.x;
    const int bt0 = blockIdx.x * 32;

    for (int idx = tid; idx < 32 * AD_; idx += 256) {
        int i = idx >> 7, k = idx & 127;
        int bt = bt0 + i;
        int b = bt / T_, t = bt - b * T_;
        af[i][k] = audio[((size_t)t * B_ + b) * AD_ + k];
    }
    __syncthreads();

    for (int c = tid; c < VD_; c += 256) {
        const float4* w4 = (const float4*)(Wa1 + (size_t)c * AD_);
        float acc[32];
#pragma unroll
        for (int i = 0; i < 32; ++i) acc[i] = 0.f;
        for (int k4 = 0; k4 < AD_ / 4; ++k4) {
            float4 w = w4[k4];
#pragma unroll
            for (int i = 0; i < 32; ++i) {
                float4 v = *(const float4*)&af[i][k4 * 4];
                acc[i] += v.x * w.x + v.y * w.y + v.z * w.z + v.w * w.w;
            }
        }
        float bias = ba1[c];
#pragma unroll
        for (int i = 0; i < 32; ++i)
            g_aq1[(size_t)(bt0 + i) * VD_ + c] = fmaxf(acc[i] + bias, 0.f);
    }
    {
        int j = tid;
        const float4* w4 = (const float4*)(Wa2 + (size_t)j * AD_);
        float acc[32];
#pragma unroll
        for (int i = 0; i < 32; ++i) acc[i] = 0.f;
        for (int k4 = 0; k4 < AD_ / 4; ++k4) {
            float4 w = w4[k4];
#pragma unroll
            for (int i = 0; i < 32; ++i) {
                float4 v = *(const float4*)&af[i][k4 * 4];
                acc[i] += v.x * w.x + v.y * w.y + v.z * w.z + v.w * w.w;
            }
        }
        float bias = ba2[j];
#pragma unroll
        for (int i = 0; i < 32; ++i)
            g_aq2[(size_t)(bt0 + i) * HD_ + j] = fmaxf(acc[i] + bias, 0.f);
    }
}

// ---------------------------------------------------------------------------
// Shared GEMM mainloop, M=128 (clip pair: rows 0-48 clip0, 64-112 clip1),
// N=128, double-buffered K=64 chunks. 8 warps = 2(M) x 4(N), warp M64 x N32.
// ---------------------------------------------------------------------------
__device__ __forceinline__ void convert_A_pair(
    char* A_h, char* A_l, const float* __restrict__ video,
    const float* scale0, const float* scale1,
    int bt0, int kc, int tid)
{
    for (int idx = tid; idx < 98 * 16; idx += 256) {
        int r = idx >> 4, q = idx & 15;
        int clip = (r >= 49);
        int h = r - clip * 49;
        int pr = r + clip * 15;          // physical row (pad rows 49-63 skipped)
        float4 v = *(const float4*)(video +
            ((size_t)(bt0 + clip) * HW_ + h) * VD_ + kc * 64 + q * 4);
        if (scale0) {
            const float* sc = clip ? scale1 : scale0;
            float4 s = *(const float4*)(sc + kc * 64 + q * 4);
            v.x *= s.x; v.y *= s.y; v.z *= s.z; v.w *= s.w;
        }
        split_store(A_h, A_l, pr, q, v.x, v.y, v.z, v.w);
    }
}

__device__ __forceinline__ void gemm_mainloop_pair(
    float acc[4][4][4], char* sm, uint32_t aBase,
    const float* __restrict__ video,
    const float* scale0, const float* scale1,
    const __nv_bfloat16* wImgH, const __nv_bfloat16* wImgL,
    int bt0, int tid, int lane, int wm, int wn)
{
    // zero pad rows (phys 49-63 and 113-127) in BOTH buffers, hi+lo
    for (int i = tid; i < 2 * 30 * 36; i += 256) {
        int b = i / (30 * 36), rr = (i / 36) % 30, o = (i % 36) * 4;
        int pr = (rr < 15) ? (49 + rr) : (113 - 15 + rr);
        char* base = sm + b * BUF_BYTES;
        *(uint32_t*)(base + pr * ROWB + o) = 0u;
        *(uint32_t*)(base + 18432 + pr * ROWB + o) = 0u;
    }

    // per-lane ldmatrix offsets (relative to buffer base)
    const uint32_t oAh = (uint32_t)((wm * 64 + (lane & 15)) * ROWB
                        + ((lane >> 4) & 1) * 16);
    const uint32_t oBh = 36864u
                        + (uint32_t)((wn * 32 + (lane & 7) + ((lane >> 4) & 1) * 8) * ROWB
                        + ((lane >> 3) & 1) * 16);

    // prologue: chunk 0 into buffer 0
    convert_A_pair(sm, sm + 18432, video, scale0, scale1, bt0, 0, tid);
    {
        const char* sH = (const char*)wImgH;
        const char* sL = (const char*)wImgL;
        for (int off = tid * 16; off < 18432; off += 4096) {
            cp16(aBase + 36864 + off, sH + off);
            cp16(aBase + 55296 + off, sL + off);
        }
    }
    CP_COMMIT();

    for (int kc = 0; kc < 8; ++kc) {
        const int p = kc & 1;
        const uint32_t bp = aBase + p * BUF_BYTES;
        CP_WAIT0();
        __syncthreads();   // chunk kc ready; buffer p^1 free to overwrite

        if (kc < 7) {
            const uint32_t bq = aBase + (p ^ 1) * BUF_BYTES;
            const char* sH = (const char*)(wImgH + (size_t)(kc + 1) * CHUNK_ELEMS);
            const char* sL = (const char*)(wImgL + (size_t)(kc + 1) * CHUNK_ELEMS);
            for (int off = tid * 16; off < 18432; off += 4096) {
                cp16(bq + 36864 + off, sH + off);
                cp16(bq + 55296 + off, sL + off);
            }
            CP_COMMIT();
            char* q = sm + (p ^ 1) * BUF_BYTES;
            convert_A_pair(q, q + 18432, video, scale0, scale1, bt0, kc + 1, tid);
        }

        // MMA on chunk kc (buffer p)
#pragma unroll
        for (int ks = 0; ks < 4; ++ks) {
            uint32_t bh[2][4], bl[2][4];
#pragma unroll
            for (int np = 0; np < 2; ++np) {
                ldmx4(bp + oBh + np * MT_STRIDE + ks * 32, bh[np]);
                ldmx4(bp + oBh + 18432 + np * MT_STRIDE + ks * 32, bl[np]);
            }
#pragma unroll
            for (int mt = 0; mt < 4; ++mt) {
                uint32_t ah[4], al[4];
                ldmx4(bp + oAh + mt * MT_STRIDE + ks * 32, ah);
                ldmx4(bp + oAh + 18432 + mt * MT_STRIDE + ks * 32, al);
#pragma unroll
                for (int nt = 0; nt < 4; ++nt) {
                    int np = nt >> 1, s = (nt & 1) * 2;
                    mma_bf16(acc[mt][nt], ah, bh[np][s], bh[np][s + 1]);
                    mma_bf16(acc[mt][nt], al, bh[np][s], bh[np][s + 1]);
                    mma_bf16(acc[mt][nt], ah, bl[np][s], bl[np][s + 1]);
                }
            }
        }
    }
    __syncthreads();
}

// ---------------------------------------------------------------------------
// g1: GEMM1 + relu + hw-mean + x aq1/49 -> g_m1.  grid = (4 nc, 1280 pairs)
// ---------------------------------------------------------------------------
__global__ void __launch_bounds__(256)
g1_mma(const float* __restrict__ video, const float* __restrict__ bv1)
{
    extern __shared__ char sm[];
    const int tid = threadIdx.x, wid = tid >> 5, lane = tid & 31;
    const int wm = wid >> 2, wn = wid & 3;
    const int nc = blockIdx.x, bt0 = blockIdx.y * 2;
    const uint32_t aBase = smem_u32(sm);

    float acc[4][4][4];
#pragma unroll
    for (int a = 0; a < 4; ++a)
#pragma unroll
        for (int b = 0; b < 4; ++b)
#pragma unroll
            for (int c = 0; c < 4; ++c) acc[a][b][c] = 0.f;

    gemm_mainloop_pair(acc, sm, aBase, video, nullptr, nullptr,
                       g_W1h + (size_t)nc * 8 * CHUNK_ELEMS,
                       g_W1l + (size_t)nc * 8 * CHUNK_ELEMS,
                       bt0, tid, lane, wm, wn);

    // stage relu(D + bias) into smem [128][132]
    float* stage = (float*)sm;
#pragma unroll
    for (int mt = 0; mt < 4; ++mt)
#pragma unroll
        for (int nt = 0; nt < 4; ++nt) {
            int r0 = wm * 64 + mt * 16 + (lane >> 2);
            int c0 = wn * 32 + nt * 8 + (lane & 3) * 2;
            float b0 = bv1[nc * 128 + c0], b1 = bv1[nc * 128 + c0 + 1];
            stage[r0 * 132 + c0]           = fmaxf(acc[mt][nt][0] + b0, 0.f);
            stage[r0 * 132 + c0 + 1]       = fmaxf(acc[mt][nt][1] + b1, 0.f);
            stage[(r0 + 8) * 132 + c0]     = fmaxf(acc[mt][nt][2] + b0, 0.f);
            stage[(r0 + 8) * 132 + c0 + 1] = fmaxf(acc[mt][nt][3] + b1, 0.f);
        }
    __syncthreads();

    {
        int clip = tid >> 7, col = tid & 127;
        float s = 0.f;
#pragma unroll
        for (int h = 0; h < HW_; ++h) s += stage[(clip * 64 + h) * 132 + col];
        int bt = bt0 + clip, c = nc * 128 + col;
        g_m1[(size_t)bt * VD_ + c] =
            g_aq1[(size_t)bt * VD_ + c] * s * (1.f / 49.f);
    }
}

// ---------------------------------------------------------------------------
// k3: channel-attention MLP, 16 clips/block (weight reads amortized 2x more,
// 160 blocks -> better SM coverage)
// ---------------------------------------------------------------------------
__global__ void __launch_bounds__(256)
k3_catt(const float* __restrict__ Wb, const float* __restrict__ bb,
        const float* __restrict__ Wc, const float* __restrict__ bc)
{
    __shared__ __align__(16) float m1s[16][VD_];
    __shared__ __align__(16) float t1s[16][HD_];
    const int tid = threadIdx.x;
    const int bt0 = blockIdx.x * 16;

    {
        const float4* src = (const float4*)(g_m1 + (size_t)bt0 * VD_);
        float4* dst = (float4*)m1s;
        for (int i = tid; i < 16 * VD_ / 4; i += 256) dst[i] = src[i];
    }
    __syncthreads();
    {
        int j = tid;
        const float4* w4 = (const float4*)(Wb + (size_t)j * VD_);
        float acc[16];
#pragma unroll
        for (int i = 0; i < 16; ++i) acc[i] = 0.f;
        for (int k4 = 0; k4 < VD_ / 4; ++k4) {
            float4 w = w4[k4];
#pragma unroll
            for (int i = 0; i < 16; ++i) {
                float4 v = *(const float4*)&m1s[i][k4 * 4];
                acc[i] += v.x * w.x + v.y * w.y + v.z * w.z + v.w * w.w;
            }
        }
        float bias = bb[j];
#pragma unroll
        for (int i = 0; i < 16; ++i) t1s[i][j] = fmaxf(acc[i] + bias, 0.f);
    }
    __syncthreads();
    for (int c = tid; c < VD_; c += 256) {
        const float4* w4 = (const float4*)(Wc + (size_t)c * HD_);
        float acc[16];
#pragma unroll
        for (int i = 0; i < 16; ++i) acc[i] = 0.f;
        for (int k4 = 0; k4 < HD_ / 4; ++k4) {
            float4 w = w4[k4];
#pragma unroll
            for (int i = 0; i < 16; ++i) {
                float4 v = *(const float4*)&t1s[i][k4 * 4];
                acc[i] += v.x * w.x + v.y * w.y + v.z * w.z + v.w * w.w;
            }
        }
        float bias = bc[c];
#pragma unroll
        for (int i = 0; i < 16; ++i) {
            float x = acc[i] + bias;
            g_scale[(size_t)(bt0 + i) * VD_ + c] = 1.f + 1.f / (1.f + expf(-x));
        }
    }
}

// ---------------------------------------------------------------------------
// g2: GEMM2 + relu x (aq2*Ws) row partials -> g_part.  grid = (2 nh, 1280)
// ---------------------------------------------------------------------------
__global__ void __launch_bounds__(256)
g2_mma(const float* __restrict__ video, const float* __restrict__ bv2,
       const float* __restrict__ Ws)
{
    extern __shared__ char sm[];
    __shared__ float u_s[2][128];
    __shared__ float part[128];
    const int tid = threadIdx.x, wid = tid >> 5, lane = tid & 31;
    const int wm = wid >> 2, wn = wid & 3;
    const int nh = blockIdx.x, bt0 = blockIdx.y * 2;
    const uint32_t aBase = smem_u32(sm);

    {
        int clip = tid >> 7, j = tid & 127;
        u_s[clip][j] = g_aq2[(size_t)(bt0 + clip) * HD_ + nh * 128 + j]
                     * Ws[nh * 128 + j];
    }
    if (tid < 128) part[tid] = 0.f;

    float acc[4][4][4];
#pragma unroll
    for (int a = 0; a < 4; ++a)
#pragma unroll
        for (int b = 0; b < 4; ++b)
#pragma unroll
            for (int c = 0; c < 4; ++c) acc[a][b][c] = 0.f;

    gemm_mainloop_pair(acc, sm, aBase, video,
                       g_scale + (size_t)bt0 * VD_,
                       g_scale + (size_t)(bt0 + 1) * VD_,
                       g_W2h + (size_t)nh * 8 * CHUNK_ELEMS,
                       g_W2l + (size_t)nh * 8 * CHUNK_ELEMS,
                       bt0, tid, lane, wm, wn);

    // row partials: sum_j relu(D + bv2[j]) * u[j]   (clip = wm)
#pragma unroll
    for (int mt = 0; mt < 4; ++mt) {
        int r0 = wm * 64 + mt * 16 + (lane >> 2);
        float s0 = 0.f, s1 = 0.f;
#pragma unroll
        for (int nt = 0; nt < 4; ++nt) {
            int c0 = wn * 32 + nt * 8 + (lane & 3) * 2;
            float b0 = bv2[nh * 128 + c0], b1 = bv2[nh * 128 + c0 + 1];
            float u0 = u_s[wm][c0], u1 = u_s[wm][c0 + 1];
            s0 += fmaxf(acc[mt][nt][0] + b0, 0.f) * u0
                + fmaxf(acc[mt][nt][1] + b1, 0.f) * u1;
            s1 += fmaxf(acc[mt][nt][2] + b0, 0.f) * u0
                + fmaxf(acc[mt][nt][3] + b1, 0.f) * u1;
        }
        s0 += __shfl_xor_sync(0xffffffffu, s0, 1);
        s0 += __shfl_xor_sync(0xffffffffu, s0, 2);
        s1 += __shfl_xor_sync(0xffffffffu, s1, 1);
        s1 += __shfl_xor_sync(0xffffffffu, s1, 2);
        if ((lane & 3) == 0) {
            atomicAdd(&part[r0], s0);
            atomicAdd(&part[r0 + 8], s1);
        }
    }
    __syncthreads();
    if (tid < 128) {
        int clip = tid >> 6, h = tid & 63;
        g_part[((size_t)(bt0 + clip) * 2 + nh) * 64 + h] = part[tid];
    }
}

// ---------------------------------------------------------------------------
// k5: tanh + softmax + output contraction (unchanged)
// ---------------------------------------------------------------------------
__global__ void __launch_bounds__(128)
k5_out(const float* __restrict__ video, const float* __restrict__ bs,
       float* __restrict__ out)
{
    __shared__ float swt[64];
    __shared__ float smx, sdn;
    const int tid = threadIdx.x;
    const int bt = blockIdx.x;

    if (tid < HW_)
        swt[tid] = tanhf(g_part[((size_t)bt * 2) * 64 + tid]
                       + g_part[((size_t)bt * 2 + 1) * 64 + tid] + bs[0]);
    __syncthreads();
    if (tid == 0) {
        float mx = -1e30f;
        for (int h = 0; h < HW_; ++h) mx = fmaxf(mx, swt[h]);
        float den = 0.f;
        for (int h = 0; h < HW_; ++h) den += expf(swt[h] - mx);
        smx = mx; sdn = den;
    }
    __syncthreads();
    if (tid < HW_) swt[tid] = expf(swt[tid] - smx) / sdn;
    __syncthreads();

    for (int c = tid; c < VD_; c += 128) {
        float a = 0.f;
#pragma unroll 7
        for (int h = 0; h < HW_; ++h)
            a += swt[h] * video[((size_t)bt * HW_ + h) * VD_ + c];
        out[(size_t)bt * VD_ + c] = a * g_scale[(size_t)bt * VD_ + c];
    }
}

// ---------------------------------------------------------------------------
// Launch
// ---------------------------------------------------------------------------
extern "C" void kernel_launch(void* const* d_in, const int* in_sizes, int n_in,
                              void* d_out, int out_size)
{
    const float* video = (const float*)d_in[0];
    const float* audio = (const float*)d_in[1];
    const float* Wv1   = (const float*)d_in[2];
    const float* bv1   = (const float*)d_in[3];
    const float* Wa1   = (const float*)d_in[4];
    const float* ba1   = (const float*)d_in[5];
    const float* Wb    = (const float*)d_in[6];
    const float* bb    = (const float*)d_in[7];
    const float* Wc    = (const float*)d_in[8];
    const float* bc    = (const float*)d_in[9];
    const float* Wv2   = (const float*)d_in[10];
    const float* bv2   = (const float*)d_in[11];
    const float* Wa2   = (const float*)d_in[12];
    const float* ba2   = (const float*)d_in[13];
    const float* Ws    = (const float*)d_in[14];
    const float* bs    = (const float*)d_in[15];
    float* out = (float*)d_out;

    cudaFuncSetAttribute(g1_mma, cudaFuncAttributeMaxDynamicSharedMemorySize, SMEM_TOT);
    cudaFuncSetAttribute(g2_mma, cudaFuncAttributeMaxDynamicSharedMemorySize, SMEM_TOT);

    k0_wconv<<<1536, 256>>>(Wv1, Wv2);
    k1_audio<<<BT_ / 32, 256>>>(audio, Wa1, ba1, Wa2, ba2);
    g1_mma<<<dim3(4, BT_ / 2), 256, SMEM_TOT>>>(video, bv1);
    k3_catt<<<BT_ / 16, 256>>>(Wb, bb, Wc, bc);
    g2_mma<<<dim3(2, BT_ / 2), 256, SMEM_TOT>>>(video, bv2, Ws);
    k5_out<<<BT_, 128>>>(video, bs, out);
}

// round 10
// speedup vs baseline: 1.8540x; 1.8540x over previous
#include <cuda_runtime.h>
#include <cuda_bf16.h>
#include <cstdint>

#define B_   256
#define T_   10
#define BT_  2560
#define HW_  49
#define VD_  512
#define AD_  128
#define HD_  256

// ---------------------------------------------------------------------------
// Scratch (__device__ globals — allocation-free)
// ---------------------------------------------------------------------------
__device__ float g_aq1[BT_ * VD_];
__device__ float g_aq2[BT_ * HD_];
__device__ float g_m1 [BT_ * VD_];
__device__ float g_scale[BT_ * VD_];
__device__ float g_part[BT_ * 64];       // complete per-clip row sums

// Pre-split bf16 weight images: [n_chunk][k_chunk(8)][128 n-rows][72 k]
__device__ __align__(16) __nv_bfloat16 g_W1h[4 * 8 * 128 * 72];
__device__ __align__(16) __nv_bfloat16 g_W1l[4 * 8 * 128 * 72];
__device__ __align__(16) __nv_bfloat16 g_W2h[2 * 8 * 128 * 72];
__device__ __align__(16) __nv_bfloat16 g_W2l[2 * 8 * 128 * 72];

#define CHUNK_ELEMS (128 * 72)
#define ROWB 144                         // smem row stride (72 bf16)
#define MT_STRIDE (16 * ROWB)

// SMEM layout (dynamic, 92160 B): A_h@0 (9216) A_l@9216 (9216)
//                                 W_h@18432 (36864) W_l@55296 (36864)
#define SM_AL 9216
#define SM_WH 18432
#define SM_WL 55296
#define SMEM_BYTES 92160

// ---------------------------------------------------------------------------
// Helpers (plain sm_103-safe PTX only)
// ---------------------------------------------------------------------------
__device__ __forceinline__ uint32_t smem_u32(const void* p) {
    uint32_t a;
    asm("{ .reg .u64 t; cvta.to.shared.u64 t, %1; cvt.u32.u64 %0, t; }"
        : "=r"(a) : "l"(p));
    return a;
}
__device__ __forceinline__ void ldmx4(uint32_t addr, uint32_t r[4]) {
    asm volatile("ldmatrix.sync.aligned.m8n8.x4.shared.b16 {%0,%1,%2,%3}, [%4];"
                 : "=r"(r[0]), "=r"(r[1]), "=r"(r[2]), "=r"(r[3]) : "r"(addr));
}
__device__ __forceinline__ void mma_bf16(float d[4], const uint32_t a[4],
                                         uint32_t b0, uint32_t b1) {
    asm volatile(
        "mma.sync.aligned.m16n8k16.row.col.f32.bf16.bf16.f32 "
        "{%0,%1,%2,%3},{%4,%5,%6,%7},{%8,%9},{%0,%1,%2,%3};"
        : "+f"(d[0]), "+f"(d[1]), "+f"(d[2]), "+f"(d[3])
        : "r"(a[0]), "r"(a[1]), "r"(a[2]), "r"(a[3]), "r"(b0), "r"(b1));
}
__device__ __forceinline__ void cp16(uint32_t dst, const void* src) {
    asm volatile("cp.async.cg.shared.global [%0], [%1], 16;" :: "r"(dst), "l"(src));
}
__device__ __forceinline__ void cp_commit_wait() {
    asm volatile("cp.async.commit_group;" ::: "memory");
    asm volatile("cp.async.wait_group 0;" ::: "memory");
}

__device__ __forceinline__ void split_store(char* Ah, char* Al, int r, int q,
                                            float x0, float x1, float x2, float x3) {
    __nv_bfloat16 h0 = __float2bfloat16(x0), h1 = __float2bfloat16(x1);
    __nv_bfloat16 h2 = __float2bfloat16(x2), h3 = __float2bfloat16(x3);
    __nv_bfloat16 l0 = __float2bfloat16(x0 - __bfloat162float(h0));
    __nv_bfloat16 l1 = __float2bfloat16(x1 - __bfloat162float(h1));
    __nv_bfloat16 l2 = __float2bfloat16(x2 - __bfloat162float(h2));
    __nv_bfloat16 l3 = __float2bfloat16(x3 - __bfloat162float(h3));
    __nv_bfloat162 p;
    char* dh = Ah + r * ROWB + q * 8;
    char* dl = Al + r * ROWB + q * 8;
    p.x = h0; p.y = h1; *(__nv_bfloat162*)dh = p;
    p.x = h2; p.y = h3; *(__nv_bfloat162*)(dh + 4) = p;
    p.x = l0; p.y = l1; *(__nv_bfloat162*)dl = p;
    p.x = l2; p.y = l3; *(__nv_bfloat162*)(dl + 4) = p;
}

// ---------------------------------------------------------------------------
// k0: split Wv1/Wv2 into bf16 hi/lo padded tile images (proven)
// ---------------------------------------------------------------------------
__global__ void __launch_bounds__(256)
k0_wconv(const float* __restrict__ Wv1, const float* __restrict__ Wv2)
{
    int idx = blockIdx.x * 256 + threadIdx.x;
    if (idx < 512 * 512) {
        int c = idx >> 9, k = idx & 511;
        float v = Wv1[idx];
        __nv_bfloat16 h = __float2bfloat16(v);
        __nv_bfloat16 l = __float2bfloat16(v - __bfloat162float(h));
        int nc = c >> 7, nl = c & 127, kc = k >> 6, kk = k & 63;
        size_t d = ((size_t)(nc * 8 + kc) * 128 + nl) * 72 + kk;
        g_W1h[d] = h; g_W1l[d] = l;
    } else if (idx < 512 * 512 + 256 * 512) {
        int e = idx - 512 * 512;
        int j = e >> 9, k = e & 511;
        float v = Wv2[e];
        __nv_bfloat16 h = __float2bfloat16(v);
        __nv_bfloat16 l = __float2bfloat16(v - __bfloat162float(h));
        int nc = j >> 7, nl = j & 127, kc = k >> 6, kk = k & 63;
        size_t d = ((size_t)(nc * 8 + kc) * 128 + nl) * 72 + kk;
        g_W2h[d] = h; g_W2l[d] = l;
    }
}

// ---------------------------------------------------------------------------
// k1: audio features (proven, unchanged)
// ---------------------------------------------------------------------------
__global__ void __launch_bounds__(256)
k1_audio(const float* __restrict__ audio,
         const float* __restrict__ Wa1, const float* __restrict__ ba1,
         const float* __restrict__ Wa2, const float* __restrict__ ba2)
{
    __shared__ __align__(16) float af[32][AD_];
    const int tid = threadIdx.x;
    const int bt0 = blockIdx.x * 32;

    for (int idx = tid; idx < 32 * AD_; idx += 256) {
        int i = idx >> 7, k = idx & 127;
        int bt = bt0 + i;
        int b = bt / T_, t = bt - b * T_;
        af[i][k] = audio[((size_t)t * B_ + b) * AD_ + k];
    }
    __syncthreads();

    for (int c = tid; c < VD_; c += 256) {
        const float4* w4 = (const float4*)(Wa1 + (size_t)c * AD_);
        float acc[32];
#pragma unroll
        for (int i = 0; i < 32; ++i) acc[i] = 0.f;
        for (int k4 = 0; k4 < AD_ / 4; ++k4) {
            float4 w = w4[k4];
#pragma unroll
            for (int i = 0; i < 32; ++i) {
                float4 v = *(const float4*)&af[i][k4 * 4];
                acc[i] += v.x * w.x + v.y * w.y + v.z * w.z + v.w * w.w;
            }
        }
        float bias = ba1[c];
#pragma unroll
        for (int i = 0; i < 32; ++i)
            g_aq1[(size_t)(bt0 + i) * VD_ + c] = fmaxf(acc[i] + bias, 0.f);
    }
    {
        int j = tid;
        const float4* w4 = (const float4*)(Wa2 + (size_t)j * AD_);
        float acc[32];
#pragma unroll
        for (int i = 0; i < 32; ++i) acc[i] = 0.f;
        for (int k4 = 0; k4 < AD_ / 4; ++k4) {
            float4 w = w4[k4];
#pragma unroll
            for (int i = 0; i < 32; ++i) {
                float4 v = *(const float4*)&af[i][k4 * 4];
                acc[i] += v.x * w.x + v.y * w.y + v.z * w.z + v.w * w.w;
            }
        }
        float bias = ba2[j];
#pragma unroll
        for (int i = 0; i < 32; ++i)
            g_aq2[(size_t)(bt0 + i) * HD_ + j] = fmaxf(acc[i] + bias, 0.f);
    }
}

// ---------------------------------------------------------------------------
// GEMM mainloop: M=64 (one clip), N=256, K chunks of 64, single buffer,
// 2 CTAs/SM. A converted in-loop from video (R7-proven path); W from two
// 128-row image chunk sequences (wH0/wH1 = smem rows 0-127 / 128-255).
// 8 warps = 2(M) x 4(N); each warp M32 x N64. acc[2 mt][8 nt][4].
// ---------------------------------------------------------------------------
__device__ __forceinline__ void gemm_mainloop(
    float acc[2][8][4], char* sm, uint32_t aBase,
    const float* __restrict__ video, const float* scale /*nullptr or clip row*/,
    const __nv_bfloat16* wH0, const __nv_bfloat16* wL0,
    const __nv_bfloat16* wH1, const __nv_bfloat16* wL1,
    int bt, int tid, int lane, int wm, int wn)
{
    char* A_h = sm;
    char* A_l = sm + SM_AL;

    // zero pad rows 49..63 of A (hi+lo), once
    for (int i = tid; i < 540; i += 256) {
        int r = 49 + i / 36, o = (i % 36) * 4;
        *(uint32_t*)(A_h + r * ROWB + o) = 0u;
        *(uint32_t*)(A_l + r * ROWB + o) = 0u;
    }

    // per-lane ldmatrix base addresses (R7-proven formulas; N base wn*64)
    const uint32_t pAh = aBase + (uint32_t)((wm * 32 + (lane & 15)) * ROWB
                        + ((lane >> 4) & 1) * 16);
    const uint32_t pAl = pAh + SM_AL;
    const uint32_t pBh = aBase + SM_WH
                        + (uint32_t)((wn * 64 + (lane & 7) + ((lane >> 4) & 1) * 8) * ROWB
                        + ((lane >> 3) & 1) * 16);
    const uint32_t pBl = pBh + (SM_WL - SM_WH);

    for (int kc = 0; kc < 8; ++kc) {
        __syncthreads();   // prior chunk's ldmatrix reads done before overwrite
        // W chunk: two 18432B images per component -> 36864B smem region
        {
            const char* sH0 = (const char*)(wH0 + (size_t)kc * CHUNK_ELEMS);
            const char* sH1 = (const char*)(wH1 + (size_t)kc * CHUNK_ELEMS);
            const char* sL0 = (const char*)(wL0 + (size_t)kc * CHUNK_ELEMS);
            const char* sL1 = (const char*)(wL1 + (size_t)kc * CHUNK_ELEMS);
            for (int off = tid * 16; off < 18432; off += 4096) {
                cp16(aBase + SM_WH + off,         sH0 + off);
                cp16(aBase + SM_WH + 18432 + off, sH1 + off);
                cp16(aBase + SM_WL + off,         sL0 + off);
                cp16(aBase + SM_WL + 18432 + off, sL1 + off);
            }
        }
        // A chunk: convert 49 x 64 fp32 -> bf16 hi/lo (optionally x scale)
        for (int idx = tid; idx < 49 * 16; idx += 256) {
            int r = idx >> 4, q = idx & 15;
            float4 v = *(const float4*)(video +
                ((size_t)bt * HW_ + r) * VD_ + kc * 64 + q * 4);
            if (scale) {
                float4 s = *(const float4*)(scale + kc * 64 + q * 4);
                v.x *= s.x; v.y *= s.y; v.z *= s.z; v.w *= s.w;
            }
            split_store(A_h, A_l, r, q, v.x, v.y, v.z, v.w);
        }
        cp_commit_wait();
        __syncthreads();

        // MMA on chunk kc
#pragma unroll
        for (int ks = 0; ks < 4; ++ks) {
            uint32_t ah[2][4], al[2][4];
#pragma unroll
            for (int mt = 0; mt < 2; ++mt) {
                ldmx4(pAh + mt * MT_STRIDE + ks * 32, ah[mt]);
                ldmx4(pAl + mt * MT_STRIDE + ks * 32, al[mt]);
            }
#pragma unroll
            for (int np = 0; np < 4; ++np) {
                uint32_t bh4[4], bl4[4];
                ldmx4(pBh + np * MT_STRIDE + ks * 32, bh4);
                ldmx4(pBl + np * MT_STRIDE + ks * 32, bl4);
#pragma unroll
                for (int mt = 0; mt < 2; ++mt)
#pragma unroll
                    for (int sub = 0; sub < 2; ++sub) {
                        int nt = np * 2 + sub, s = sub * 2;
                        mma_bf16(acc[mt][nt], ah[mt], bh4[s], bh4[s + 1]);
                        mma_bf16(acc[mt][nt], al[mt], bh4[s], bh4[s + 1]);
                        mma_bf16(acc[mt][nt], ah[mt], bl4[s], bl4[s + 1]);
                    }
            }
        }
    }
    __syncthreads();   // smem free for epilogue reuse
}

// ---------------------------------------------------------------------------
// g1: GEMM1 + relu + hw-mean + x aq1/49 -> g_m1.  grid = (2 n-halves, 2560)
// ---------------------------------------------------------------------------
__global__ void __launch_bounds__(256, 2)
g1_mma(const float* __restrict__ video, const float* __restrict__ bv1)
{
    extern __shared__ char sm[];
    const int tid = threadIdx.x, wid = tid >> 5, lane = tid & 31;
    const int wm = wid >> 2, wn = wid & 3;
    const int nh = blockIdx.x, bt = blockIdx.y;
    const uint32_t aBase = smem_u32(sm);

    float acc[2][8][4];
#pragma unroll
    for (int a = 0; a < 2; ++a)
#pragma unroll
        for (int b = 0; b < 8; ++b)
#pragma unroll
            for (int c = 0; c < 4; ++c) acc[a][b][c] = 0.f;

    gemm_mainloop(acc, sm, aBase, video, nullptr,
                  g_W1h + (size_t)(nh * 2)     * 8 * CHUNK_ELEMS,
                  g_W1l + (size_t)(nh * 2)     * 8 * CHUNK_ELEMS,
                  g_W1h + (size_t)(nh * 2 + 1) * 8 * CHUNK_ELEMS,
                  g_W1l + (size_t)(nh * 2 + 1) * 8 * CHUNK_ELEMS,
                  bt, tid, lane, wm, wn);

    // stage relu(D + bias) into smem [64][260]
    float* stage = (float*)sm;
#pragma unroll
    for (int mt = 0; mt < 2; ++mt)
#pragma unroll
        for (int nt = 0; nt < 8; ++nt) {
            int r0 = wm * 32 + mt * 16 + (lane >> 2);
            int c0 = wn * 64 + nt * 8 + (lane & 3) * 2;
            float b0 = bv1[nh * 256 + c0], b1 = bv1[nh * 256 + c0 + 1];
            stage[r0 * 260 + c0]           = fmaxf(acc[mt][nt][0] + b0, 0.f);
            stage[r0 * 260 + c0 + 1]       = fmaxf(acc[mt][nt][1] + b1, 0.f);
            stage[(r0 + 8) * 260 + c0]     = fmaxf(acc[mt][nt][2] + b0, 0.f);
            stage[(r0 + 8) * 260 + c0 + 1] = fmaxf(acc[mt][nt][3] + b1, 0.f);
        }
    __syncthreads();

    {
        float s = 0.f;
#pragma unroll
        for (int h = 0; h < HW_; ++h) s += stage[h * 260 + tid];
        int c = nh * 256 + tid;
        g_m1[(size_t)bt * VD_ + c] =
            g_aq1[(size_t)bt * VD_ + c] * s * (1.f / 49.f);
    }
}

// ---------------------------------------------------------------------------
// k3: channel-attention MLP, 16 clips/block (R8-proven)
// ---------------------------------------------------------------------------
__global__ void __launch_bounds__(256)
k3_catt(const float* __restrict__ Wb, const float* __restrict__ bb,
        const float* __restrict__ Wc, const float* __restrict__ bc)
{
    __shared__ __align__(16) float m1s[16][VD_];
    __shared__ __align__(16) float t1s[16][HD_];
    const int tid = threadIdx.x;
    const int bt0 = blockIdx.x * 16;

    {
        const float4* src = (const float4*)(g_m1 + (size_t)bt0 * VD_);
        float4* dst = (float4*)m1s;
        for (int i = tid; i < 16 * VD_ / 4; i += 256) dst[i] = src[i];
    }
    __syncthreads();
    {
        int j = tid;
        const float4* w4 = (const float4*)(Wb + (size_t)j * VD_);
        float acc[16];
#pragma unroll
        for (int i = 0; i < 16; ++i) acc[i] = 0.f;
        for (int k4 = 0; k4 < VD_ / 4; ++k4) {
            float4 w = w4[k4];
#pragma unroll
            for (int i = 0; i < 16; ++i) {
                float4 v = *(const float4*)&m1s[i][k4 * 4];
                acc[i] += v.x * w.x + v.y * w.y + v.z * w.z + v.w * w.w;
            }
        }
        float bias = bb[j];
#pragma unroll
        for (int i = 0; i < 16; ++i) t1s[i][j] = fmaxf(acc[i] + bias, 0.f);
    }
    __syncthreads();
    for (int c = tid; c < VD_; c += 256) {
        const float4* w4 = (const float4*)(Wc + (size_t)c * HD_);
        float acc[16];
#pragma unroll
        for (int i = 0; i < 16; ++i) acc[i] = 0.f;
        for (int k4 = 0; k4 < HD_ / 4; ++k4) {
            float4 w = w4[k4];
#pragma unroll
            for (int i = 0; i < 16; ++i) {
                float4 v = *(const float4*)&t1s[i][k4 * 4];
                acc[i] += v.x * w.x + v.y * w.y + v.z * w.z + v.w * w.w;
            }
        }
        float bias = bc[c];
#pragma unroll
        for (int i = 0; i < 16; ++i) {
            float x = acc[i] + bias;
            g_scale[(size_t)(bt0 + i) * VD_ + c] = 1.f + 1.f / (1.f + expf(-x));
        }
    }
}

// ---------------------------------------------------------------------------
// g2: GEMM2 (full N=256 in one block) + relu x (aq2*Ws) row sums -> g_part
// grid = 2560
// ---------------------------------------------------------------------------
__global__ void __launch_bounds__(256, 2)
g2_mma(const float* __restrict__ video, const float* __restrict__ bv2,
       const float* __restrict__ Ws)
{
    extern __shared__ char sm[];
    __shared__ float u_s[256];
    __shared__ float part[64];
    const int tid = threadIdx.x, wid = tid >> 5, lane = tid & 31;
    const int wm = wid >> 2, wn = wid & 3;
    const int bt = blockIdx.x;
    const uint32_t aBase = smem_u32(sm);

    u_s[tid] = g_aq2[(size_t)bt * HD_ + tid] * Ws[tid];
    if (tid < 64) part[tid] = 0.f;

    float acc[2][8][4];
#pragma unroll
    for (int a = 0; a < 2; ++a)
#pragma unroll
        for (int b = 0; b < 8; ++b)
#pragma unroll
            for (int c = 0; c < 4; ++c) acc[a][b][c] = 0.f;

    gemm_mainloop(acc, sm, aBase, video, g_scale + (size_t)bt * VD_,
                  g_W2h, g_W2l,
                  g_W2h + (size_t)8 * CHUNK_ELEMS,
                  g_W2l + (size_t)8 * CHUNK_ELEMS,
                  bt, tid, lane, wm, wn);

    // row sums: sum_j relu(D + bv2[j]) * u[j]
#pragma unroll
    for (int mt = 0; mt < 2; ++mt) {
        int r0 = wm * 32 + mt * 16 + (lane >> 2);
        float s0 = 0.f, s1 = 0.f;
#pragma unroll
        for (int nt = 0; nt < 8; ++nt) {
            int c0 = wn * 64 + nt * 8 + (lane & 3) * 2;
            float b0 = bv2[c0], b1 = bv2[c0 + 1];
            float u0 = u_s[c0], u1 = u_s[c0 + 1];
            s0 += fmaxf(acc[mt][nt][0] + b0, 0.f) * u0
                + fmaxf(acc[mt][nt][1] + b1, 0.f) * u1;
            s1 += fmaxf(acc[mt][nt][2] + b0, 0.f) * u0
                + fmaxf(acc[mt][nt][3] + b1, 0.f) * u1;
        }
        s0 += __shfl_xor_sync(0xffffffffu, s0, 1);
        s0 += __shfl_xor_sync(0xffffffffu, s0, 2);
        s1 += __shfl_xor_sync(0xffffffffu, s1, 1);
        s1 += __shfl_xor_sync(0xffffffffu, s1, 2);
        if ((lane & 3) == 0) {
            atomicAdd(&part[r0], s0);
            atomicAdd(&part[r0 + 8], s1);
        }
    }
    __syncthreads();
    if (tid < 64)
        g_part[(size_t)bt * 64 + tid] = part[tid];
}

// ---------------------------------------------------------------------------
// k5: tanh + softmax + output contraction
// ---------------------------------------------------------------------------
__global__ void __launch_bounds__(128)
k5_out(const float* __restrict__ video, const float* __restrict__ bs,
       float* __restrict__ out)
{
    __shared__ float swt[64];
    __shared__ float smx, sdn;
    const int tid = threadIdx.x;
    const int bt = blockIdx.x;

    if (tid < HW_)
        swt[tid] = tanhf(g_part[(size_t)bt * 64 + tid] + bs[0]);
    __syncthreads();
    if (tid == 0) {
        float mx = -1e30f;
        for (int h = 0; h < HW_; ++h) mx = fmaxf(mx, swt[h]);
        float den = 0.f;
        for (int h = 0; h < HW_; ++h) den += expf(swt[h] - mx);
        smx = mx; sdn = den;
    }
    __syncthreads();
    if (tid < HW_) swt[tid] = expf(swt[tid] - smx) / sdn;
    __syncthreads();

    for (int c = tid; c < VD_; c += 128) {
        float a = 0.f;
#pragma unroll 7
        for (int h = 0; h < HW_; ++h)
            a += swt[h] * video[((size_t)bt * HW_ + h) * VD_ + c];
        out[(size_t)bt * VD_ + c] = a * g_scale[(size_t)bt * VD_ + c];
    }
}

// ---------------------------------------------------------------------------
// Launch
// ---------------------------------------------------------------------------
extern "C" void kernel_launch(void* const* d_in, const int* in_sizes, int n_in,
                              void* d_out, int out_size)
{
    const float* video = (const float*)d_in[0];
    const float* audio = (const float*)d_in[1];
    const float* Wv1   = (const float*)d_in[2];
    const float* bv1   = (const float*)d_in[3];
    const float* Wa1   = (const float*)d_in[4];
    const float* ba1   = (const float*)d_in[5];
    const float* Wb    = (const float*)d_in[6];
    const float* bb    = (const float*)d_in[7];
    const float* Wc    = (const float*)d_in[8];
    const float* bc    = (const float*)d_in[9];
    const float* Wv2   = (const float*)d_in[10];
    const float* bv2   = (const float*)d_in[11];
    const float* Wa2   = (const float*)d_in[12];
    const float* ba2   = (const float*)d_in[13];
    const float* Ws    = (const float*)d_in[14];
    const float* bs    = (const float*)d_in[15];
    float* out = (float*)d_out;

    cudaFuncSetAttribute(g1_mma, cudaFuncAttributeMaxDynamicSharedMemorySize, SMEM_BYTES);
    cudaFuncSetAttribute(g2_mma, cudaFuncAttributeMaxDynamicSharedMemorySize, SMEM_BYTES);

    k0_wconv<<<1536, 256>>>(Wv1, Wv2);
    k1_audio<<<BT_ / 32, 256>>>(audio, Wa1, ba1, Wa2, ba2);
    g1_mma<<<dim3(2, BT_), 256, SMEM_BYTES>>>(video, bv1);
    k3_catt<<<BT_ / 16, 256>>>(Wb, bb, Wc, bc);
    g2_mma<<<BT_, 256, SMEM_BYTES>>>(video, bv2, Ws);
    k5_out<<<BT_, 128>>>(video, bs, out);
}